// round 13
// baseline (speedup 1.0000x reference)
#include <cuda_runtime.h>
#include <math.h>
#include <stdint.h>

#define NN 10000
#define EE 160000
#define DD 128
#define HH 4
#define HC 512
#define STRD 2564            // fused node-feature stride: q|k|v|skip|qWe|qbe
#define QOFF 0
#define KOFF 512
#define VOFF 1024
#define SKOFF 1536
#define QWEOFF 2048
#define QBEOFF 2560
#define RSQRT_D 0.08838834764831845f  // 1/sqrt(128)
#define BPAD 136

// ---------------- scratch (device globals; no runtime allocation) -----------
__device__ float    g_nodes[NN * STRD];   // fused per-node features
__device__ float    g_Wcat[DD * STRD];    // concatenated weights (fp32)
__device__ float    g_bcat[STRD];         // concatenated bias
__device__ uint32_t g_Ahi[NN * DD];       // x pre-split to tf32 hi/lo
__device__ uint32_t g_Alo[NN * DD];
__device__ uint32_t g_Bhi0[DD * STRD];    // Wcat pre-split to tf32 hi/lo
__device__ uint32_t g_Blo0[DD * STRD];
__device__ float    g_aggv[NN * HC];      // softmax-weighted v aggregate
__device__ float    g_t[NN * HC];         // softmax-weighted edge_attr aggregate
__device__ float    g_agge[NN * HC];      // t @ We (+ gated be)
__device__ float    g_normed[NN * HC];
__device__ int      g_count[NN];
__device__ int      g_off[NN];
__device__ int      g_cur[NN];
__device__ int      g_elist[EE];
__device__ int      g_esrc[EE];
__device__ int      g_is64;

// ---- edge-index accessor: dtype decided at runtime, indices clamped --------
__device__ __forceinline__ int load_idx(const void* ei, int is64, long long pos) {
    int v = is64 ? (int)((const long long*)ei)[pos] : ((const int*)ei)[pos];
    return min(max(v, 0), NN - 1);
}

__global__ void detect_kernel(const void* ei) {
    if (threadIdx.x == 0 && blockIdx.x == 0) {
        const int* p = (const int*)ei;
        int orv = 0;
        for (int i = 1; i < 2048; i += 2) orv |= p[i];
        g_is64 = (orv == 0) ? 1 : 0;
    }
}

__global__ void zero_kernel() {
    int t = blockIdx.x * 256 + threadIdx.x;
    if (t < NN) g_count[t] = 0;
}

__device__ __forceinline__ uint32_t f2tf(float v) {
    uint32_t r;
    asm("cvt.rna.tf32.f32 %0, %1;" : "=r"(r) : "f"(v));
    return r;
}

// ---------------- weight prep: build Wcat / bcat -----------------------------
__global__ __launch_bounds__(128) void prep_kernel(
    const float* __restrict__ Wq, const float* __restrict__ bq,
    const float* __restrict__ Wk, const float* __restrict__ bk,
    const float* __restrict__ Wv, const float* __restrict__ bv,
    const float* __restrict__ We, const float* __restrict__ be,
    const float* __restrict__ Wskip, const float* __restrict__ bskip) {
    int c = blockIdx.x, t = threadIdx.x;
    __shared__ float wrow[128];
    float val, bias = 0.f;
    if (c < 512)       { val = Wq[t * HC + c];            bias = bq[c]; }
    else if (c < 1024) { val = Wk[t * HC + c - 512];      bias = bk[c - 512]; }
    else if (c < 1536) { val = Wv[t * HC + c - 1024];     bias = bv[c - 1024]; }
    else if (c < 2048) { val = Wskip[t * HC + c - 1536];  bias = bskip[c - 1536]; }
    else if (c < 2560) {
        int cc = c - 2048, h = cc >> 7, m = cc & 127;
        wrow[t] = We[m * HC + h * 128 + t];
        __syncthreads();
        float acc = 0.f;
        for (int d = 0; d < 128; d++) acc += Wq[t * HC + h * 128 + d] * wrow[d];
        val = acc;
        if (t == 0) {
            float bacc = 0.f;
            for (int d = 0; d < 128; d++) bacc += bq[h * 128 + d] * wrow[d];
            bias = bacc;
        }
    } else {
        int h = c - 2560;
        float acc = 0.f;
        for (int d = 0; d < 128; d++) acc += Wq[t * HC + h * 128 + d] * be[h * 128 + d];
        val = acc;
        if (t == 0) {
            float bacc = 0.f;
            for (int d = 0; d < 128; d++) bacc += bq[h * 128 + d] * be[h * 128 + d];
            bias = bacc;
        }
    }
    g_Wcat[t * STRD + c] = val;
    uint32_t hi = f2tf(val);
    g_Bhi0[t * STRD + c] = hi;
    g_Blo0[t * STRD + c] = f2tf(val - __uint_as_float(hi));
    if (t == 0) g_bcat[c] = bias;
}

// ---------------- pre-split x to tf32 hi/lo ----------------------------------
__global__ void split_x_kernel(const float* __restrict__ x) {
    int t = blockIdx.x * 256 + threadIdx.x;
    if (t < NN * DD) {
        float v = x[t];
        uint32_t hi = f2tf(v);
        g_Ahi[t] = hi;
        g_Alo[t] = f2tf(v - __uint_as_float(hi));
    }
}

// ---------------- tensor-core SGEMM (3xTF32, fp32-grade accuracy) ------------
__device__ __forceinline__ void mma8(float* c, const uint32_t* a, uint32_t b0, uint32_t b1) {
    asm volatile(
        "mma.sync.aligned.m16n8k8.row.col.f32.tf32.tf32.f32 "
        "{%0,%1,%2,%3}, {%4,%5,%6,%7}, {%8,%9}, {%0,%1,%2,%3};"
        : "+f"(c[0]), "+f"(c[1]), "+f"(c[2]), "+f"(c[3])
        : "r"(a[0]), "r"(a[1]), "r"(a[2]), "r"(a[3]), "r"(b0), "r"(b1));
}

// SEL 0: g_nodes = x @ Wcat + bcat           (K=128, N=2564, pre-split operands)
// SEL 4: g_agge  = g_t(head) @ We + gated be (K=128, N=512, head = by)
// SEL 5: d_out   = elu(g_normed @ Wlin + blin + x) (K=512, N=128)
template <int SEL>
__global__ __launch_bounds__(256, 2) void sgemm_tc(
    const float* __restrict__ Bin,
    const float* __restrict__ biasin, const float* __restrict__ xres,
    float* __restrict__ Cout) {
    constexpr int K    = (SEL == 5) ? 512 : 128;
    constexpr int NTOT = (SEL == 0) ? STRD : (SEL == 4) ? HC : DD;
    constexpr int BS   = NTOT;
    const float* A = (SEL == 4) ? g_t : g_normed;   // fp32 A (SEL4/5 only)
    const float* bias_p = (SEL == 0) ? g_bcat : biasin;
    float* C = (SEL == 0) ? g_nodes : (SEL == 4) ? g_agge : Cout;

    __shared__ uint32_t sm[4 * 16 * BPAD];   // Ahi|Alo|Bhi|Blo; reused as stage
    uint32_t* sAhi = sm;
    uint32_t* sAlo = sm + 16 * BPAD;
    uint32_t* sBhi = sm + 2 * 16 * BPAD;
    uint32_t* sBlo = sm + 3 * 16 * BPAD;

    int tid = threadIdx.x;
    int lane = tid & 31, w = tid >> 5;
    int g = lane >> 2, tig = lane & 3;
    int wm = w & 3, wn = w >> 2;
    int m0 = wm * 32, n0 = wn * 64;
    int row0 = blockIdx.x * 128;
    int col0 = blockIdx.y * 128;
    const int acb = (SEL == 4) ? col0 : 0;

    float acc[2][8][4];
#pragma unroll
    for (int mt = 0; mt < 2; mt++)
#pragma unroll
        for (int nt = 0; nt < 8; nt++)
#pragma unroll
            for (int r = 0; r < 4; r++) acc[mt][nt][r] = 0.f;

    for (int kb = 0; kb < K; kb += 16) {
        __syncthreads();
        if (SEL == 0) {
#pragma unroll
            for (int i = 0; i < 2; i++) {
                int qi = tid + i * 256;
                int m = qi >> 2, kq = qi & 3;
                int r = row0 + m;
                uint4 hv = make_uint4(0, 0, 0, 0), lv = make_uint4(0, 0, 0, 0);
                if (r < NN) {
                    hv = *(const uint4*)&g_Ahi[(size_t)r * DD + kb + kq * 4];
                    lv = *(const uint4*)&g_Alo[(size_t)r * DD + kb + kq * 4];
                }
                uint32_t hvv[4] = {hv.x, hv.y, hv.z, hv.w};
                uint32_t lvv[4] = {lv.x, lv.y, lv.z, lv.w};
#pragma unroll
                for (int j = 0; j < 4; j++) {
                    int kk = kq * 4 + j;
                    int idx = kk * BPAD + (m ^ ((kk >> 2) << 3));
                    sAhi[idx] = hvv[j];
                    sAlo[idx] = lvv[j];
                }
            }
#pragma unroll
            for (int i = 0; i < 2; i++) {
                int qi = tid + i * 256;
                int kk = qi >> 5, nq = qi & 31;
                int c = col0 + nq * 4;
                uint4 bh = make_uint4(0, 0, 0, 0), bl = make_uint4(0, 0, 0, 0);
                if (c + 4 <= NTOT) {
                    bh = *(const uint4*)&g_Bhi0[(size_t)(kb + kk) * STRD + c];
                    bl = *(const uint4*)&g_Blo0[(size_t)(kb + kk) * STRD + c];
                }
                *(uint4*)&sBhi[kk * BPAD + nq * 4] = bh;
                *(uint4*)&sBlo[kk * BPAD + nq * 4] = bl;
            }
        } else {
#pragma unroll
            for (int i = 0; i < 2; i++) {
                int qi = tid + i * 256;
                int m = qi >> 2, kq = qi & 3;
                int r = row0 + m;
                float4 av = make_float4(0.f, 0.f, 0.f, 0.f);
                if (r < NN) av = *(const float4*)&A[(size_t)r * HC + acb + kb + kq * 4];
                float vv[4] = {av.x, av.y, av.z, av.w};
#pragma unroll
                for (int j = 0; j < 4; j++) {
                    int kk = kq * 4 + j;
                    uint32_t hi = f2tf(vv[j]);
                    float lo = vv[j] - __uint_as_float(hi);
                    int idx = kk * BPAD + (m ^ ((kk >> 2) << 3));
                    sAhi[idx] = hi;
                    sAlo[idx] = f2tf(lo);
                }
            }
#pragma unroll
            for (int i = 0; i < 2; i++) {
                int qi = tid + i * 256;
                int kk = qi >> 5, nq = qi & 31;
                int c = col0 + nq * 4;
                float4 bv = make_float4(0.f, 0.f, 0.f, 0.f);
                if (c + 4 <= NTOT) bv = *(const float4*)&Bin[(size_t)(kb + kk) * BS + c];
                float vv[4] = {bv.x, bv.y, bv.z, bv.w};
#pragma unroll
                for (int j = 0; j < 4; j++) {
                    uint32_t hi = f2tf(vv[j]);
                    float lo = vv[j] - __uint_as_float(hi);
                    sBhi[kk * BPAD + nq * 4 + j] = hi;
                    sBlo[kk * BPAD + nq * 4 + j] = f2tf(lo);
                }
            }
        }
        __syncthreads();
#pragma unroll
        for (int ks = 0; ks < 2; ks++) {
            int rlo = ks * 8 + tig, rhi = ks * 8 + tig + 4;
            int s1 = (rlo >> 2) << 3, s2 = (rhi >> 2) << 3;
            uint32_t ahi[2][4], alo[2][4];
#pragma unroll
            for (int mt = 0; mt < 2; mt++) {
                int mb = m0 + mt * 16 + g;
                ahi[mt][0] = sAhi[rlo * BPAD + (mb ^ s1)];
                ahi[mt][1] = sAhi[rlo * BPAD + ((mb + 8) ^ s1)];
                ahi[mt][2] = sAhi[rhi * BPAD + (mb ^ s2)];
                ahi[mt][3] = sAhi[rhi * BPAD + ((mb + 8) ^ s2)];
                alo[mt][0] = sAlo[rlo * BPAD + (mb ^ s1)];
                alo[mt][1] = sAlo[rlo * BPAD + ((mb + 8) ^ s1)];
                alo[mt][2] = sAlo[rhi * BPAD + (mb ^ s2)];
                alo[mt][3] = sAlo[rhi * BPAD + ((mb + 8) ^ s2)];
            }
#pragma unroll
            for (int nt = 0; nt < 8; nt++) {
                int nb = n0 + nt * 8 + g;
                uint32_t bh0 = sBhi[rlo * BPAD + nb];
                uint32_t bh1 = sBhi[rhi * BPAD + nb];
                uint32_t bl0 = sBlo[rlo * BPAD + nb];
                uint32_t bl1 = sBlo[rhi * BPAD + nb];
#pragma unroll
                for (int mt = 0; mt < 2; mt++) {
                    mma8(acc[mt][nt], ahi[mt], bl0, bl1);
                    mma8(acc[mt][nt], alo[mt], bh0, bh1);
                    mma8(acc[mt][nt], ahi[mt], bh0, bh1);
                }
            }
        }
    }

    float* stg = (float*)sm;   // 128 x 68
#pragma unroll
    for (int p = 0; p < 2; p++) {
        __syncthreads();
        if (wn == p) {
#pragma unroll
            for (int mt = 0; mt < 2; mt++)
#pragma unroll
                for (int nt = 0; nt < 8; nt++) {
                    int rl = m0 + mt * 16 + g;
                    int cl = nt * 8 + tig * 2;
                    stg[rl * 68 + cl]           = acc[mt][nt][0];
                    stg[rl * 68 + cl + 1]       = acc[mt][nt][1];
                    stg[(rl + 8) * 68 + cl]     = acc[mt][nt][2];
                    stg[(rl + 8) * 68 + cl + 1] = acc[mt][nt][3];
                }
        }
        __syncthreads();
#pragma unroll
        for (int i = 0; i < 8; i++) {
            int qi = tid + i * 256;
            int rl = qi >> 4, q4 = qi & 15;
            int grow = row0 + rl;
            int gcol = col0 + p * 64 + q4 * 4;
            if (grow < NN && gcol + 4 <= NTOT) {
                float4 v = *(float4*)&stg[rl * 68 + q4 * 4];
                float gate = 1.f;
                if (SEL == 4) gate = (g_count[grow] > 0) ? 1.f : 0.f;
                float o[4] = {v.x, v.y, v.z, v.w};
#pragma unroll
                for (int j = 0; j < 4; j++) {
                    o[j] += gate * bias_p[gcol + j];
                    if (SEL == 5) {
                        o[j] += xres[(size_t)grow * DD + gcol + j];
                        o[j] = (o[j] > 0.f) ? o[j] : expm1f(o[j]);
                    }
                }
                *(float4*)&C[(size_t)grow * BS + gcol] = make_float4(o[0], o[1], o[2], o[3]);
            }
        }
    }
}

// ---------------- CSR build (int atomics only, in-bounds by clamp) -----------
__global__ void hist_kernel(const void* __restrict__ ei) {
    int t = blockIdx.x * 256 + threadIdx.x;
    if (t < EE) {
        int d = load_idx(ei, g_is64, (long long)EE + t);
        atomicAdd(&g_count[d], 1);
    }
}

__global__ __launch_bounds__(1024) void scan_kernel() {
    __shared__ int sh[1024];
    int t = threadIdx.x;
    int loc[16];
    int s = 0;
#pragma unroll
    for (int i = 0; i < 16; i++) {
        int idx = t * 16 + i;
        int cv = (idx < NN) ? g_count[idx] : 0;
        loc[i] = cv; s += cv;
    }
    sh[t] = s;
    __syncthreads();
    for (int off = 1; off < 1024; off <<= 1) {
        int v = (t >= off) ? sh[t - off] : 0;
        __syncthreads();
        sh[t] += v;
        __syncthreads();
    }
    int excl = sh[t] - s;
#pragma unroll
    for (int i = 0; i < 16; i++) {
        int idx = t * 16 + i;
        if (idx < NN) {
            g_off[idx] = excl;
            g_cur[idx] = excl;
            excl += loc[i];
        }
    }
}

__global__ void fill_kernel(const void* __restrict__ ei) {
    int t = blockIdx.x * 256 + threadIdx.x;
    if (t < EE) {
        int is64 = g_is64;
        int d = load_idx(ei, is64, (long long)EE + t);
        int pos = atomicAdd(&g_cur[d], 1);
        pos = min(max(pos, 0), EE - 1);
        g_elist[pos] = t;
        g_esrc[pos]  = load_idx(ei, is64, t);
    }
}

// ---------------- fused edge pass: warp-autonomous, coalesced, 2-edge ILP ----
// One block (128 thr, 4 warps) per dst node; each warp owns edges w, w+4, ...
// and processes them in PAIRS: all 18 float4 gathers for both edges are
// issued before any arithmetic (double MLP); the two butterfly reductions
// interleave so shfl latency of one edge overlaps FMA of the other.
// Lane l owns cols h*128+4*lane for all heads (warp-contiguous requests).
// ea loaded once per edge, reused for alpha + t-accum. Denominator factored
// out (identical math to reference).
__global__ __launch_bounds__(128) void agg_fused_kernel(const float* __restrict__ ea) {
    int n = blockIdx.x;
    int l = threadIdx.x;
    int lane = l & 31, w = l >> 5;
    int off = g_off[n], cnt = g_count[n];
    int c4 = 4 * lane;

    float4 q[4], qw[4];
    float qbe[4];
#pragma unroll
    for (int h = 0; h < 4; h++) {
        q[h]  = *(const float4*)&g_nodes[(size_t)n * STRD + QOFF + h * 128 + c4];
        qw[h] = *(const float4*)&g_nodes[(size_t)n * STRD + QWEOFF + h * 128 + c4];
        qbe[h] = g_nodes[(size_t)n * STRD + QBEOFF + h];
    }

    float den[4] = {0.f, 0.f, 0.f, 0.f};
    float4 av[4], at[4];
#pragma unroll
    for (int h = 0; h < 4; h++) {
        av[h] = make_float4(0.f, 0.f, 0.f, 0.f);
        at[h] = make_float4(0.f, 0.f, 0.f, 0.f);
    }

    int k = w;
    for (; k + 4 < cnt; k += 8) {
        int s0   = g_esrc[off + k],     s1   = g_esrc[off + k + 4];
        int eid0 = g_elist[off + k],    eid1 = g_elist[off + k + 4];
        // issue ALL gathers for both edges first
        float4 ea0 = __ldg((const float4*)&ea[(size_t)eid0 * DD + c4]);
        float4 ea1 = __ldg((const float4*)&ea[(size_t)eid1 * DD + c4]);
        float4 kk0[4], vv0[4], kk1[4], vv1[4];
#pragma unroll
        for (int h = 0; h < 4; h++) {
            kk0[h] = __ldg((const float4*)&g_nodes[(size_t)s0 * STRD + KOFF + h * 128 + c4]);
            kk1[h] = __ldg((const float4*)&g_nodes[(size_t)s1 * STRD + KOFF + h * 128 + c4]);
            vv0[h] = __ldg((const float4*)&g_nodes[(size_t)s0 * STRD + VOFF + h * 128 + c4]);
            vv1[h] = __ldg((const float4*)&g_nodes[(size_t)s1 * STRD + VOFF + h * 128 + c4]);
        }
        float p0[4], p1[4];
#pragma unroll
        for (int h = 0; h < 4; h++) {
            p0[h] = q[h].x * kk0[h].x + q[h].y * kk0[h].y
                  + q[h].z * kk0[h].z + q[h].w * kk0[h].w
                  + qw[h].x * ea0.x + qw[h].y * ea0.y
                  + qw[h].z * ea0.z + qw[h].w * ea0.w;
            p1[h] = q[h].x * kk1[h].x + q[h].y * kk1[h].y
                  + q[h].z * kk1[h].z + q[h].w * kk1[h].w
                  + qw[h].x * ea1.x + qw[h].y * ea1.y
                  + qw[h].z * ea1.z + qw[h].w * ea1.w;
        }
#pragma unroll
        for (int offs = 16; offs > 0; offs >>= 1) {
#pragma unroll
            for (int h = 0; h < 4; h++) {
                p0[h] += __shfl_xor_sync(0xffffffffu, p0[h], offs);
                p1[h] += __shfl_xor_sync(0xffffffffu, p1[h], offs);
            }
        }
#pragma unroll
        for (int h = 0; h < 4; h++) {
            float e0 = expf((p0[h] + qbe[h]) * RSQRT_D);
            float e1 = expf((p1[h] + qbe[h]) * RSQRT_D);
            den[h] += e0 + e1;
            av[h].x += e0 * vv0[h].x + e1 * vv1[h].x;
            av[h].y += e0 * vv0[h].y + e1 * vv1[h].y;
            av[h].z += e0 * vv0[h].z + e1 * vv1[h].z;
            av[h].w += e0 * vv0[h].w + e1 * vv1[h].w;
            at[h].x += e0 * ea0.x + e1 * ea1.x;
            at[h].y += e0 * ea0.y + e1 * ea1.y;
            at[h].z += e0 * ea0.z + e1 * ea1.z;
            at[h].w += e0 * ea0.w + e1 * ea1.w;
        }
    }
    if (k < cnt) {
        int s   = g_esrc[off + k];
        int eid = g_elist[off + k];
        float4 ea4 = __ldg((const float4*)&ea[(size_t)eid * DD + c4]);
        float4 kk[4], vv[4];
#pragma unroll
        for (int h = 0; h < 4; h++) {
            kk[h] = __ldg((const float4*)&g_nodes[(size_t)s * STRD + KOFF + h * 128 + c4]);
            vv[h] = __ldg((const float4*)&g_nodes[(size_t)s * STRD + VOFF + h * 128 + c4]);
        }
        float p[4];
#pragma unroll
        for (int h = 0; h < 4; h++) {
            p[h] = q[h].x * kk[h].x + q[h].y * kk[h].y
                 + q[h].z * kk[h].z + q[h].w * kk[h].w
                 + qw[h].x * ea4.x + qw[h].y * ea4.y
                 + qw[h].z * ea4.z + qw[h].w * ea4.w;
        }
#pragma unroll
        for (int offs = 16; offs > 0; offs >>= 1) {
#pragma unroll
            for (int h = 0; h < 4; h++)
                p[h] += __shfl_xor_sync(0xffffffffu, p[h], offs);
        }
#pragma unroll
        for (int h = 0; h < 4; h++) {
            float e0 = expf((p[h] + qbe[h]) * RSQRT_D);
            den[h] += e0;
            av[h].x += e0 * vv[h].x; av[h].y += e0 * vv[h].y;
            av[h].z += e0 * vv[h].z; av[h].w += e0 * vv[h].w;
            at[h].x += e0 * ea4.x;   at[h].y += e0 * ea4.y;
            at[h].z += e0 * ea4.z;   at[h].w += e0 * ea4.w;
        }
    }

    // merge 4 warps via smem
    __shared__ float sv[4][HC], st_[4][HC];
    __shared__ float sd[4][HH];
#pragma unroll
    for (int h = 0; h < 4; h++) {
        *(float4*)&sv[w][h * 128 + c4]  = av[h];
        *(float4*)&st_[w][h * 128 + c4] = at[h];
    }
    if (lane < 4) sd[w][lane] = den[lane];
    __syncthreads();

    int ho = l >> 5;
    float d = sd[0][ho] + sd[1][ho] + sd[2][ho] + sd[3][ho];
    float rd = (cnt > 0) ? 1.f / d : 0.f;
    float4 rv = make_float4(0.f, 0.f, 0.f, 0.f), rt = make_float4(0.f, 0.f, 0.f, 0.f);
#pragma unroll
    for (int ww = 0; ww < 4; ww++) {
        float4 a = *(float4*)&sv[ww][4 * l];
        float4 b = *(float4*)&st_[ww][4 * l];
        rv.x += a.x; rv.y += a.y; rv.z += a.z; rv.w += a.w;
        rt.x += b.x; rt.y += b.y; rt.z += b.z; rt.w += b.w;
    }
    *(float4*)&g_aggv[(size_t)n * HC + 4 * l] =
        make_float4(rv.x * rd, rv.y * rd, rv.z * rd, rv.w * rd);
    *(float4*)&g_t[(size_t)n * HC + 4 * l] =
        make_float4(rt.x * rd, rt.y * rd, rt.z * rd, rt.w * rd);
}

// ---------------- LayerNorm over HC=512 (aggv + agge + skip) -----------------
__global__ __launch_bounds__(128) void ln_kernel(
    const float* __restrict__ g, const float* __restrict__ b) {
    int n = blockIdx.x;
    int tid = threadIdx.x;
    float vals[4];
    float s = 0.f, s2 = 0.f;
#pragma unroll
    for (int j = 0; j < 4; j++) {
        int c = tid + j * 128;
        float o = g_aggv[(size_t)n * HC + c] + g_agge[(size_t)n * HC + c]
                + g_nodes[(size_t)n * STRD + SKOFF + c];
        vals[j] = o; s += o; s2 += o * o;
    }
    __shared__ float sh[8];
#pragma unroll
    for (int off = 16; off > 0; off >>= 1) {
        s  += __shfl_xor_sync(0xffffffffu, s, off);
        s2 += __shfl_xor_sync(0xffffffffu, s2, off);
    }
    int wid = tid >> 5, lane = tid & 31;
    if (lane == 0) { sh[wid] = s; sh[4 + wid] = s2; }
    __syncthreads();
    s  = sh[0] + sh[1] + sh[2] + sh[3];
    s2 = sh[4] + sh[5] + sh[6] + sh[7];
    float mu = s * (1.f / 512.f);
    float var = s2 * (1.f / 512.f) - mu * mu;
    float rs = rsqrtf(var + 1e-5f);
#pragma unroll
    for (int j = 0; j < 4; j++) {
        int c = tid + j * 128;
        g_normed[(size_t)n * HC + c] = (vals[j] - mu) * rs * g[c] + b[c];
    }
}

// ---------------- launch -----------------------------------------------------
extern "C" void kernel_launch(void* const* d_in, const int* in_sizes, int n_in,
                              void* d_out, int out_size) {
    const float* x     = (const float*)d_in[0];
    const void*  ei    = d_in[1];
    const float* ea    = (const float*)d_in[2];
    const float* Wq    = (const float*)d_in[3];
    const float* bq    = (const float*)d_in[4];
    const float* Wk    = (const float*)d_in[5];
    const float* bk    = (const float*)d_in[6];
    const float* Wv    = (const float*)d_in[7];
    const float* bv    = (const float*)d_in[8];
    const float* We    = (const float*)d_in[9];
    const float* be    = (const float*)d_in[10];
    const float* Wskip = (const float*)d_in[11];
    const float* bskip = (const float*)d_in[12];
    const float* ln_g  = (const float*)d_in[13];
    const float* ln_b  = (const float*)d_in[14];
    const float* Wlin  = (const float*)d_in[15];
    const float* blin  = (const float*)d_in[16];

    detect_kernel<<<1, 32>>>(ei);
    zero_kernel<<<(NN + 255) / 256, 256>>>();
    prep_kernel<<<STRD, 128>>>(Wq, bq, Wk, bk, Wv, bv, We, be, Wskip, bskip);
    split_x_kernel<<<(NN * DD + 255) / 256, 256>>>(x);

    dim3 g0((NN + 127) / 128, (STRD + 127) / 128);
    sgemm_tc<0><<<g0, 256>>>(nullptr, nullptr, nullptr, nullptr);

    hist_kernel<<<(EE + 255) / 256, 256>>>(ei);
    scan_kernel<<<1, 1024>>>();
    fill_kernel<<<(EE + 255) / 256, 256>>>(ei);

    agg_fused_kernel<<<NN, 128>>>(ea);

    dim3 g4((NN + 127) / 128, HC / 128);
    sgemm_tc<4><<<g4, 256>>>(We, be, nullptr, nullptr);

    ln_kernel<<<NN, 128>>>(ln_g, ln_b);

    dim3 g5((NN + 127) / 128, 1);
    sgemm_tc<5><<<g5, 256>>>(Wlin, blin, x, (float*)d_out);
}

// round 15
// speedup vs baseline: 1.0163x; 1.0163x over previous
#include <cuda_runtime.h>
#include <math.h>
#include <stdint.h>

#define NN 10000
#define EE 160000
#define DD 128
#define HH 4
#define HC 512
#define STRD 2564            // fused node-feature stride: q|k|v|skip|qWe|qbe
#define QOFF 0
#define KOFF 512
#define VOFF 1024
#define SKOFF 1536
#define QWEOFF 2048
#define QBEOFF 2560
#define RSQRT_D 0.08838834764831845f  // 1/sqrt(128)
#define BPAD 136
#define TILEU (16 * BPAD)             // u32 elements per smem array per tile

// ---------------- scratch (device globals; no runtime allocation) -----------
__device__ float    g_nodes[NN * STRD];   // fused per-node features
__device__ float    g_Wcat[DD * STRD];    // concatenated weights (fp32)
__device__ float    g_bcat[STRD];         // concatenated bias
__device__ uint32_t g_Ahi[NN * DD];       // x pre-split to tf32 hi/lo
__device__ uint32_t g_Alo[NN * DD];
__device__ uint32_t g_Bhi0[DD * STRD];    // Wcat pre-split to tf32 hi/lo
__device__ uint32_t g_Blo0[DD * STRD];
__device__ float    g_aggv[NN * HC];      // softmax-weighted v aggregate
__device__ float    g_t[NN * HC];         // softmax-weighted edge_attr aggregate
__device__ float    g_agge[NN * HC];      // t @ We (+ gated be)
__device__ float    g_normed[NN * HC];
__device__ int      g_count[NN];
__device__ int      g_off[NN];
__device__ int      g_cur[NN];
__device__ int      g_elist[EE];
__device__ int      g_esrc[EE];
__device__ int      g_is64;

// ---- edge-index accessor: dtype decided at runtime, indices clamped --------
__device__ __forceinline__ int load_idx(const void* ei, int is64, long long pos) {
    int v = is64 ? (int)((const long long*)ei)[pos] : ((const int*)ei)[pos];
    return min(max(v, 0), NN - 1);
}

__global__ void detect_kernel(const void* ei) {
    if (threadIdx.x == 0 && blockIdx.x == 0) {
        const int* p = (const int*)ei;
        int orv = 0;
        for (int i = 1; i < 2048; i += 2) orv |= p[i];
        g_is64 = (orv == 0) ? 1 : 0;
    }
}

__global__ void zero_kernel() {
    int t = blockIdx.x * 256 + threadIdx.x;
    if (t < NN) g_count[t] = 0;
}

__device__ __forceinline__ uint32_t f2tf(float v) {
    uint32_t r;
    asm("cvt.rna.tf32.f32 %0, %1;" : "=r"(r) : "f"(v));
    return r;
}

__device__ __forceinline__ void cp16(uint32_t saddr, const void* g) {
    asm volatile("cp.async.ca.shared.global [%0], [%1], 16;" :: "r"(saddr), "l"(g));
}

// ---------------- weight prep: build Wcat / bcat -----------------------------
__global__ __launch_bounds__(128) void prep_kernel(
    const float* __restrict__ Wq, const float* __restrict__ bq,
    const float* __restrict__ Wk, const float* __restrict__ bk,
    const float* __restrict__ Wv, const float* __restrict__ bv,
    const float* __restrict__ We, const float* __restrict__ be,
    const float* __restrict__ Wskip, const float* __restrict__ bskip) {
    int c = blockIdx.x, t = threadIdx.x;
    __shared__ float wrow[128];
    float val, bias = 0.f;
    if (c < 512)       { val = Wq[t * HC + c];            bias = bq[c]; }
    else if (c < 1024) { val = Wk[t * HC + c - 512];      bias = bk[c - 512]; }
    else if (c < 1536) { val = Wv[t * HC + c - 1024];     bias = bv[c - 1024]; }
    else if (c < 2048) { val = Wskip[t * HC + c - 1536];  bias = bskip[c - 1536]; }
    else if (c < 2560) {
        int cc = c - 2048, h = cc >> 7, m = cc & 127;
        wrow[t] = We[m * HC + h * 128 + t];
        __syncthreads();
        float acc = 0.f;
        for (int d = 0; d < 128; d++) acc += Wq[t * HC + h * 128 + d] * wrow[d];
        val = acc;
        if (t == 0) {
            float bacc = 0.f;
            for (int d = 0; d < 128; d++) bacc += bq[h * 128 + d] * wrow[d];
            bias = bacc;
        }
    } else {
        int h = c - 2560;
        float acc = 0.f;
        for (int d = 0; d < 128; d++) acc += Wq[t * HC + h * 128 + d] * be[h * 128 + d];
        val = acc;
        if (t == 0) {
            float bacc = 0.f;
            for (int d = 0; d < 128; d++) bacc += bq[h * 128 + d] * be[h * 128 + d];
            bias = bacc;
        }
    }
    g_Wcat[t * STRD + c] = val;
    uint32_t hi = f2tf(val);
    g_Bhi0[t * STRD + c] = hi;
    g_Blo0[t * STRD + c] = f2tf(val - __uint_as_float(hi));
    if (t == 0) g_bcat[c] = bias;
}

// ---------------- pre-split x to tf32 hi/lo ----------------------------------
__global__ void split_x_kernel(const float* __restrict__ x) {
    int t = blockIdx.x * 256 + threadIdx.x;
    if (t < NN * DD) {
        float v = x[t];
        uint32_t hi = f2tf(v);
        g_Ahi[t] = hi;
        g_Alo[t] = f2tf(v - __uint_as_float(hi));
    }
}

// ---------------- tensor-core SGEMM (3xTF32, fp32-grade accuracy) ------------
__device__ __forceinline__ void mma8(float* c, const uint32_t* a, uint32_t b0, uint32_t b1) {
    asm volatile(
        "mma.sync.aligned.m16n8k8.row.col.f32.tf32.tf32.f32 "
        "{%0,%1,%2,%3}, {%4,%5,%6,%7}, {%8,%9}, {%0,%1,%2,%3};"
        : "+f"(c[0]), "+f"(c[1]), "+f"(c[2]), "+f"(c[3])
        : "r"(a[0]), "r"(a[1]), "r"(a[2]), "r"(a[3]), "r"(b0), "r"(b1));
}

// SEL 0: g_nodes = x @ Wcat + bcat (K=128, N=2564, pre-split, DOUBLE-BUFFERED)
// SEL 4: g_agge  = g_t(head) @ We + gated be (K=128, N=512, head = by)
// SEL 5: d_out   = elu(g_normed @ Wlin + blin + x) (K=512, N=128)
template <int SEL>
__global__ __launch_bounds__(256, 2) void sgemm_tc(
    const float* __restrict__ Bin,
    const float* __restrict__ biasin, const float* __restrict__ xres,
    float* __restrict__ Cout) {
    constexpr int K    = (SEL == 5) ? 512 : 128;
    constexpr int NTOT = (SEL == 0) ? STRD : (SEL == 4) ? HC : DD;
    constexpr int BS   = NTOT;
    const float* A = (SEL == 4) ? g_t : g_normed;   // fp32 A (SEL4/5 only)
    const float* bias_p = (SEL == 0) ? g_bcat : biasin;
    float* C = (SEL == 0) ? g_nodes : (SEL == 4) ? g_agge : Cout;

    extern __shared__ uint32_t smdyn[];

    int tid = threadIdx.x;
    int lane = tid & 31, w = tid >> 5;
    int g = lane >> 2, tig = lane & 3;
    int wm = w & 3, wn = w >> 2;
    int m0 = wm * 32, n0 = wn * 64;
    int row0 = blockIdx.x * 128;
    int col0 = blockIdx.y * 128;
    const int acb = (SEL == 4) ? col0 : 0;

    float acc[2][8][4];
#pragma unroll
    for (int mt = 0; mt < 2; mt++)
#pragma unroll
        for (int nt = 0; nt < 8; nt++)
#pragma unroll
            for (int r = 0; r < 4; r++) acc[mt][nt][r] = 0.f;

    if (SEL == 0) {
        // ----- pipelined double-buffer path -----
        uint32_t shbase = (uint32_t)__cvta_generic_to_shared(smdyn);
        uint4 ahv[2], alv[2];

        auto ldA = [&](int kb) {
#pragma unroll
            for (int i = 0; i < 2; i++) {
                int qi = tid + i * 256;
                int m = qi >> 2, kq = qi & 3;
                int r = row0 + m;
                ahv[i] = make_uint4(0, 0, 0, 0);
                alv[i] = make_uint4(0, 0, 0, 0);
                if (r < NN) {
                    ahv[i] = *(const uint4*)&g_Ahi[(size_t)r * DD + kb + kq * 4];
                    alv[i] = *(const uint4*)&g_Alo[(size_t)r * DD + kb + kq * 4];
                }
            }
        };
        auto stA = [&](int b) {
#pragma unroll
            for (int i = 0; i < 2; i++) {
                int qi = tid + i * 256;
                int m = qi >> 2, kq = qi & 3;
                uint32_t hv[4] = {ahv[i].x, ahv[i].y, ahv[i].z, ahv[i].w};
                uint32_t lv[4] = {alv[i].x, alv[i].y, alv[i].z, alv[i].w};
#pragma unroll
                for (int j = 0; j < 4; j++) {
                    int kk = kq * 4 + j;
                    int idx = (b * 4) * TILEU + kk * BPAD + (m ^ ((kk >> 2) << 3));
                    smdyn[idx] = hv[j];
                    smdyn[idx + TILEU] = lv[j];
                }
            }
        };
        auto cpB = [&](int kb, int b) {
#pragma unroll
            for (int i = 0; i < 2; i++) {
                int qi = tid + i * 256;
                int kk = qi >> 5, nq = qi & 31;
                int c = col0 + nq * 4;
                int ehi = (b * 4 + 2) * TILEU + kk * BPAD + nq * 4;
                if (c + 4 <= NTOT) {
                    cp16(shbase + ehi * 4, &g_Bhi0[(size_t)(kb + kk) * STRD + c]);
                    cp16(shbase + (ehi + TILEU) * 4, &g_Blo0[(size_t)(kb + kk) * STRD + c]);
                } else {
                    *(uint4*)&smdyn[ehi] = make_uint4(0, 0, 0, 0);
                    *(uint4*)&smdyn[ehi + TILEU] = make_uint4(0, 0, 0, 0);
                }
            }
        };

        // prologue: tile 0
        ldA(0);
        cpB(0, 0);
        asm volatile("cp.async.commit_group;");
        stA(0);
        asm volatile("cp.async.wait_group 0;");
        __syncthreads();

        const int T = K / 16;
        for (int it = 0; it < T; it++) {
            int cur = it & 1, nxt = cur ^ 1;
            bool more = (it + 1 < T);
            if (more) {
                ldA((it + 1) * 16);
                cpB((it + 1) * 16, nxt);
                asm volatile("cp.async.commit_group;");
            }
            uint32_t* sAhi = smdyn + (cur * 4) * TILEU;
            uint32_t* sAlo = sAhi + TILEU;
            uint32_t* sBhi = sAhi + 2 * TILEU;
            uint32_t* sBlo = sAhi + 3 * TILEU;
#pragma unroll
            for (int ks = 0; ks < 2; ks++) {
                int rlo = ks * 8 + tig, rhi = ks * 8 + tig + 4;
                int s1 = (rlo >> 2) << 3, s2 = (rhi >> 2) << 3;
                uint32_t ahi[2][4], alo[2][4];
#pragma unroll
                for (int mt = 0; mt < 2; mt++) {
                    int mb = m0 + mt * 16 + g;
                    ahi[mt][0] = sAhi[rlo * BPAD + (mb ^ s1)];
                    ahi[mt][1] = sAhi[rlo * BPAD + ((mb + 8) ^ s1)];
                    ahi[mt][2] = sAhi[rhi * BPAD + (mb ^ s2)];
                    ahi[mt][3] = sAhi[rhi * BPAD + ((mb + 8) ^ s2)];
                    alo[mt][0] = sAlo[rlo * BPAD + (mb ^ s1)];
                    alo[mt][1] = sAlo[rlo * BPAD + ((mb + 8) ^ s1)];
                    alo[mt][2] = sAlo[rhi * BPAD + (mb ^ s2)];
                    alo[mt][3] = sAlo[rhi * BPAD + ((mb + 8) ^ s2)];
                }
#pragma unroll
                for (int nt = 0; nt < 8; nt++) {
                    int nb = n0 + nt * 8 + g;
                    uint32_t bh0 = sBhi[rlo * BPAD + nb];
                    uint32_t bh1 = sBhi[rhi * BPAD + nb];
                    uint32_t bl0 = sBlo[rlo * BPAD + nb];
                    uint32_t bl1 = sBlo[rhi * BPAD + nb];
#pragma unroll
                    for (int mt = 0; mt < 2; mt++) {
                        mma8(acc[mt][nt], ahi[mt], bl0, bl1);
                        mma8(acc[mt][nt], alo[mt], bh0, bh1);
                        mma8(acc[mt][nt], ahi[mt], bh0, bh1);
                    }
                }
            }
            if (more) {
                stA(nxt);
                asm volatile("cp.async.wait_group 0;");
            }
            __syncthreads();
        }
    } else {
        // ----- single-buffer convert-in-kernel path (SEL4/SEL5) -----
        uint32_t* sAhi = smdyn;
        uint32_t* sAlo = smdyn + TILEU;
        uint32_t* sBhi = smdyn + 2 * TILEU;
        uint32_t* sBlo = smdyn + 3 * TILEU;
        for (int kb = 0; kb < K; kb += 16) {
            __syncthreads();
#pragma unroll
            for (int i = 0; i < 2; i++) {
                int qi = tid + i * 256;
                int m = qi >> 2, kq = qi & 3;
                int r = row0 + m;
                float4 av = make_float4(0.f, 0.f, 0.f, 0.f);
                if (r < NN) av = *(const float4*)&A[(size_t)r * HC + acb + kb + kq * 4];
                float vv[4] = {av.x, av.y, av.z, av.w};
#pragma unroll
                for (int j = 0; j < 4; j++) {
                    int kk = kq * 4 + j;
                    uint32_t hi = f2tf(vv[j]);
                    float lo = vv[j] - __uint_as_float(hi);
                    int idx = kk * BPAD + (m ^ ((kk >> 2) << 3));
                    sAhi[idx] = hi;
                    sAlo[idx] = f2tf(lo);
                }
            }
#pragma unroll
            for (int i = 0; i < 2; i++) {
                int qi = tid + i * 256;
                int kk = qi >> 5, nq = qi & 31;
                int c = col0 + nq * 4;
                float4 bv = make_float4(0.f, 0.f, 0.f, 0.f);
                if (c + 4 <= NTOT) bv = *(const float4*)&Bin[(size_t)(kb + kk) * BS + c];
                float vv[4] = {bv.x, bv.y, bv.z, bv.w};
#pragma unroll
                for (int j = 0; j < 4; j++) {
                    uint32_t hi = f2tf(vv[j]);
                    float lo = vv[j] - __uint_as_float(hi);
                    sBhi[kk * BPAD + nq * 4 + j] = hi;
                    sBlo[kk * BPAD + nq * 4 + j] = f2tf(lo);
                }
            }
            __syncthreads();
#pragma unroll
            for (int ks = 0; ks < 2; ks++) {
                int rlo = ks * 8 + tig, rhi = ks * 8 + tig + 4;
                int s1 = (rlo >> 2) << 3, s2 = (rhi >> 2) << 3;
                uint32_t ahi[2][4], alo[2][4];
#pragma unroll
                for (int mt = 0; mt < 2; mt++) {
                    int mb = m0 + mt * 16 + g;
                    ahi[mt][0] = sAhi[rlo * BPAD + (mb ^ s1)];
                    ahi[mt][1] = sAhi[rlo * BPAD + ((mb + 8) ^ s1)];
                    ahi[mt][2] = sAhi[rhi * BPAD + (mb ^ s2)];
                    ahi[mt][3] = sAhi[rhi * BPAD + ((mb + 8) ^ s2)];
                    alo[mt][0] = sAlo[rlo * BPAD + (mb ^ s1)];
                    alo[mt][1] = sAlo[rlo * BPAD + ((mb + 8) ^ s1)];
                    alo[mt][2] = sAlo[rhi * BPAD + (mb ^ s2)];
                    alo[mt][3] = sAlo[rhi * BPAD + ((mb + 8) ^ s2)];
                }
#pragma unroll
                for (int nt = 0; nt < 8; nt++) {
                    int nb = n0 + nt * 8 + g;
                    uint32_t bh0 = sBhi[rlo * BPAD + nb];
                    uint32_t bh1 = sBhi[rhi * BPAD + nb];
                    uint32_t bl0 = sBlo[rlo * BPAD + nb];
                    uint32_t bl1 = sBlo[rhi * BPAD + nb];
#pragma unroll
                    for (int mt = 0; mt < 2; mt++) {
                        mma8(acc[mt][nt], ahi[mt], bl0, bl1);
                        mma8(acc[mt][nt], alo[mt], bh0, bh1);
                        mma8(acc[mt][nt], ahi[mt], bh0, bh1);
                    }
                }
            }
        }
    }

    // ---- epilogue: stage via smem for coalesced stores ----
    float* stg = (float*)smdyn;   // 128 x 68
#pragma unroll
    for (int p = 0; p < 2; p++) {
        __syncthreads();
        if (wn == p) {
#pragma unroll
            for (int mt = 0; mt < 2; mt++)
#pragma unroll
                for (int nt = 0; nt < 8; nt++) {
                    int rl = m0 + mt * 16 + g;
                    int cl = nt * 8 + tig * 2;
                    stg[rl * 68 + cl]           = acc[mt][nt][0];
                    stg[rl * 68 + cl + 1]       = acc[mt][nt][1];
                    stg[(rl + 8) * 68 + cl]     = acc[mt][nt][2];
                    stg[(rl + 8) * 68 + cl + 1] = acc[mt][nt][3];
                }
        }
        __syncthreads();
#pragma unroll
        for (int i = 0; i < 8; i++) {
            int qi = tid + i * 256;
            int rl = qi >> 4, q4 = qi & 15;
            int grow = row0 + rl;
            int gcol = col0 + p * 64 + q4 * 4;
            if (grow < NN && gcol + 4 <= NTOT) {
                float4 v = *(float4*)&stg[rl * 68 + q4 * 4];
                float gate = 1.f;
                if (SEL == 4) gate = (g_count[grow] > 0) ? 1.f : 0.f;
                float o[4] = {v.x, v.y, v.z, v.w};
#pragma unroll
                for (int j = 0; j < 4; j++) {
                    o[j] += gate * bias_p[gcol + j];
                    if (SEL == 5) {
                        o[j] += xres[(size_t)grow * DD + gcol + j];
                        o[j] = (o[j] > 0.f) ? o[j] : expm1f(o[j]);
                    }
                }
                *(float4*)&C[(size_t)grow * BS + gcol] = make_float4(o[0], o[1], o[2], o[3]);
            }
        }
    }
}

// ---------------- CSR build (int atomics only, in-bounds by clamp) -----------
__global__ void hist_kernel(const void* __restrict__ ei) {
    int t = blockIdx.x * 256 + threadIdx.x;
    if (t < EE) {
        int d = load_idx(ei, g_is64, (long long)EE + t);
        atomicAdd(&g_count[d], 1);
    }
}

__global__ __launch_bounds__(1024) void scan_kernel() {
    __shared__ int sh[1024];
    int t = threadIdx.x;
    int loc[16];
    int s = 0;
#pragma unroll
    for (int i = 0; i < 16; i++) {
        int idx = t * 16 + i;
        int cv = (idx < NN) ? g_count[idx] : 0;
        loc[i] = cv; s += cv;
    }
    sh[t] = s;
    __syncthreads();
    for (int off = 1; off < 1024; off <<= 1) {
        int v = (t >= off) ? sh[t - off] : 0;
        __syncthreads();
        sh[t] += v;
        __syncthreads();
    }
    int excl = sh[t] - s;
#pragma unroll
    for (int i = 0; i < 16; i++) {
        int idx = t * 16 + i;
        if (idx < NN) {
            g_off[idx] = excl;
            g_cur[idx] = excl;
            excl += loc[i];
        }
    }
}

__global__ void fill_kernel(const void* __restrict__ ei) {
    int t = blockIdx.x * 256 + threadIdx.x;
    if (t < EE) {
        int is64 = g_is64;
        int d = load_idx(ei, is64, (long long)EE + t);
        int pos = atomicAdd(&g_cur[d], 1);
        pos = min(max(pos, 0), EE - 1);
        g_elist[pos] = t;
        g_esrc[pos]  = load_idx(ei, is64, t);
    }
}

// ---------------- fused edge pass: warp-autonomous + coalesced (R11) ---------
__global__ __launch_bounds__(128) void agg_fused_kernel(const float* __restrict__ ea) {
    int n = blockIdx.x;
    int l = threadIdx.x;
    int lane = l & 31, w = l >> 5;
    int off = g_off[n], cnt = g_count[n];
    int c4 = 4 * lane;

    float4 q[4], qw[4];
    float qbe[4];
#pragma unroll
    for (int h = 0; h < 4; h++) {
        q[h]  = *(const float4*)&g_nodes[(size_t)n * STRD + QOFF + h * 128 + c4];
        qw[h] = *(const float4*)&g_nodes[(size_t)n * STRD + QWEOFF + h * 128 + c4];
        qbe[h] = g_nodes[(size_t)n * STRD + QBEOFF + h];
    }

    float den[4] = {0.f, 0.f, 0.f, 0.f};
    float4 av[4], at[4];
#pragma unroll
    for (int h = 0; h < 4; h++) {
        av[h] = make_float4(0.f, 0.f, 0.f, 0.f);
        at[h] = make_float4(0.f, 0.f, 0.f, 0.f);
    }

    for (int k = w; k < cnt; k += 4) {
        int s   = g_esrc[off + k];
        int eid = g_elist[off + k];
        float4 ea4 = __ldg((const float4*)&ea[(size_t)eid * DD + c4]);
        float4 kk[4], vv[4];
#pragma unroll
        for (int h = 0; h < 4; h++) {
            kk[h] = __ldg((const float4*)&g_nodes[(size_t)s * STRD + KOFF + h * 128 + c4]);
            vv[h] = __ldg((const float4*)&g_nodes[(size_t)s * STRD + VOFF + h * 128 + c4]);
        }
        float p[4];
#pragma unroll
        for (int h = 0; h < 4; h++) {
            p[h] = q[h].x * kk[h].x + q[h].y * kk[h].y
                 + q[h].z * kk[h].z + q[h].w * kk[h].w
                 + qw[h].x * ea4.x + qw[h].y * ea4.y
                 + qw[h].z * ea4.z + qw[h].w * ea4.w;
        }
#pragma unroll
        for (int offs = 16; offs > 0; offs >>= 1) {
#pragma unroll
            for (int h = 0; h < 4; h++)
                p[h] += __shfl_xor_sync(0xffffffffu, p[h], offs);
        }
        float ex[4];
#pragma unroll
        for (int h = 0; h < 4; h++) {
            ex[h] = expf((p[h] + qbe[h]) * RSQRT_D);
            den[h] += ex[h];
            av[h].x += ex[h] * vv[h].x; av[h].y += ex[h] * vv[h].y;
            av[h].z += ex[h] * vv[h].z; av[h].w += ex[h] * vv[h].w;
            at[h].x += ex[h] * ea4.x;   at[h].y += ex[h] * ea4.y;
            at[h].z += ex[h] * ea4.z;   at[h].w += ex[h] * ea4.w;
        }
    }

    // merge 4 warps via smem
    __shared__ float sv[4][HC], st_[4][HC];
    __shared__ float sd[4][HH];
#pragma unroll
    for (int h = 0; h < 4; h++) {
        *(float4*)&sv[w][h * 128 + c4]  = av[h];
        *(float4*)&st_[w][h * 128 + c4] = at[h];
    }
    if (lane < 4) sd[w][lane] = den[lane];
    __syncthreads();

    int ho = l >> 5;
    float d = sd[0][ho] + sd[1][ho] + sd[2][ho] + sd[3][ho];
    float rd = (cnt > 0) ? 1.f / d : 0.f;
    float4 rv = make_float4(0.f, 0.f, 0.f, 0.f), rt = make_float4(0.f, 0.f, 0.f, 0.f);
#pragma unroll
    for (int ww = 0; ww < 4; ww++) {
        float4 a = *(float4*)&sv[ww][4 * l];
        float4 b = *(float4*)&st_[ww][4 * l];
        rv.x += a.x; rv.y += a.y; rv.z += a.z; rv.w += a.w;
        rt.x += b.x; rt.y += b.y; rt.z += b.z; rt.w += b.w;
    }
    *(float4*)&g_aggv[(size_t)n * HC + 4 * l] =
        make_float4(rv.x * rd, rv.y * rd, rv.z * rd, rv.w * rd);
    *(float4*)&g_t[(size_t)n * HC + 4 * l] =
        make_float4(rt.x * rd, rt.y * rd, rt.z * rd, rt.w * rd);
}

// ---------------- LayerNorm over HC=512 (aggv + agge + skip) -----------------
__global__ __launch_bounds__(128) void ln_kernel(
    const float* __restrict__ g, const float* __restrict__ b) {
    int n = blockIdx.x;
    int tid = threadIdx.x;
    float vals[4];
    float s = 0.f, s2 = 0.f;
#pragma unroll
    for (int j = 0; j < 4; j++) {
        int c = tid + j * 128;
        float o = g_aggv[(size_t)n * HC + c] + g_agge[(size_t)n * HC + c]
                + g_nodes[(size_t)n * STRD + SKOFF + c];
        vals[j] = o; s += o; s2 += o * o;
    }
    __shared__ float sh[8];
#pragma unroll
    for (int off = 16; off > 0; off >>= 1) {
        s  += __shfl_xor_sync(0xffffffffu, s, off);
        s2 += __shfl_xor_sync(0xffffffffu, s2, off);
    }
    int wid = tid >> 5, lane = tid & 31;
    if (lane == 0) { sh[wid] = s; sh[4 + wid] = s2; }
    __syncthreads();
    s  = sh[0] + sh[1] + sh[2] + sh[3];
    s2 = sh[4] + sh[5] + sh[6] + sh[7];
    float mu = s * (1.f / 512.f);
    float var = s2 * (1.f / 512.f) - mu * mu;
    float rs = rsqrtf(var + 1e-5f);
#pragma unroll
    for (int j = 0; j < 4; j++) {
        int c = tid + j * 128;
        g_normed[(size_t)n * HC + c] = (vals[j] - mu) * rs * g[c] + b[c];
    }
}

// ---------------- launch -----------------------------------------------------
extern "C" void kernel_launch(void* const* d_in, const int* in_sizes, int n_in,
                              void* d_out, int out_size) {
    const float* x     = (const float*)d_in[0];
    const void*  ei    = d_in[1];
    const float* ea    = (const float*)d_in[2];
    const float* Wq    = (const float*)d_in[3];
    const float* bq    = (const float*)d_in[4];
    const float* Wk    = (const float*)d_in[5];
    const float* bk    = (const float*)d_in[6];
    const float* Wv    = (const float*)d_in[7];
    const float* bv    = (const float*)d_in[8];
    const float* We    = (const float*)d_in[9];
    const float* be    = (const float*)d_in[10];
    const float* Wskip = (const float*)d_in[11];
    const float* bskip = (const float*)d_in[12];
    const float* ln_g  = (const float*)d_in[13];
    const float* ln_b  = (const float*)d_in[14];
    const float* Wlin  = (const float*)d_in[15];
    const float* blin  = (const float*)d_in[16];

    const int SMEM_DB = 2 * 4 * TILEU * 4;   // 69632 B (double buffer)
    const int SMEM_SB = 4 * TILEU * 4;       // 34816 B (single buffer)
    cudaFuncSetAttribute(sgemm_tc<0>, cudaFuncAttributeMaxDynamicSharedMemorySize, SMEM_DB);

    detect_kernel<<<1, 32>>>(ei);
    zero_kernel<<<(NN + 255) / 256, 256>>>();
    prep_kernel<<<STRD, 128>>>(Wq, bq, Wk, bk, Wv, bv, We, be, Wskip, bskip);
    split_x_kernel<<<(NN * DD + 255) / 256, 256>>>(x);

    dim3 g0((NN + 127) / 128, (STRD + 127) / 128);
    sgemm_tc<0><<<g0, 256, SMEM_DB>>>(nullptr, nullptr, nullptr, nullptr);

    hist_kernel<<<(EE + 255) / 256, 256>>>(ei);
    scan_kernel<<<1, 1024>>>();
    fill_kernel<<<(EE + 255) / 256, 256>>>(ei);

    agg_fused_kernel<<<NN, 128>>>(ea);

    dim3 g4((NN + 127) / 128, HC / 128);
    sgemm_tc<4><<<g4, 256, SMEM_SB>>>(We, be, nullptr, nullptr);

    ln_kernel<<<NN, 128>>>(ln_g, ln_b);

    dim3 g5((NN + 127) / 128, 1);
    sgemm_tc<5><<<g5, 256, SMEM_SB>>>(Wlin, blin, x, (float*)d_out);
}

// round 17
// speedup vs baseline: 1.0638x; 1.0467x over previous
#include <cuda_runtime.h>
#include <math.h>
#include <stdint.h>

#define NN 10000
#define EE 160000
#define DD 128
#define HH 4
#define HC 512
#define STRD 1540            // fused node features: skip | qWe | qM | dsc
#define SKOFF 0
#define QWEOFF 512
#define QMOFF 1024
#define DSCOFF 1536
#define RSQRT_D 0.08838834764831845f  // 1/sqrt(128)
#define BPAD 136
#define TILEU (16 * BPAD)

// ---------------- scratch (device globals; no runtime allocation) -----------
__device__ float    g_nodes[NN * STRD];
__device__ float    g_bcat[STRD];
__device__ uint32_t g_Ahi[NN * DD];       // x pre-split tf32 hi/lo
__device__ uint32_t g_Alo[NN * DD];
__device__ uint32_t g_Bhi0[DD * STRD];    // Wcat pre-split
__device__ uint32_t g_Blo0[DD * STRD];
__device__ float    g_ut[NN * 1024];      // per head: u (128) | t (128), 4 heads
__device__ float    g_agge[NN * HC];      // u@Wv + t@We + gated (bv+be)
__device__ float    g_normed[NN * HC];
__device__ int      g_count[NN];
__device__ int      g_off[NN];
__device__ int      g_cur[NN];
__device__ int      g_elist[EE];
__device__ int      g_esrc[EE];
__device__ int      g_is64;

__device__ __forceinline__ int load_idx(const void* ei, int is64, long long pos) {
    int v = is64 ? (int)((const long long*)ei)[pos] : ((const int*)ei)[pos];
    return min(max(v, 0), NN - 1);
}

__global__ void detect_kernel(const void* ei) {
    if (threadIdx.x == 0 && blockIdx.x == 0) {
        const int* p = (const int*)ei;
        int orv = 0;
        for (int i = 1; i < 2048; i += 2) orv |= p[i];
        g_is64 = (orv == 0) ? 1 : 0;
    }
}

__global__ void zero_kernel() {
    int t = blockIdx.x * 256 + threadIdx.x;
    if (t < NN) g_count[t] = 0;
}

__device__ __forceinline__ uint32_t f2tf(float v) {
    uint32_t r;
    asm("cvt.rna.tf32.f32 %0, %1;" : "=r"(r) : "f"(v));
    return r;
}

__device__ __forceinline__ void cp16(uint32_t saddr, const void* g) {
    asm volatile("cp.async.ca.shared.global [%0], [%1], 16;" :: "r"(saddr), "l"(g));
}

// ---------------- weight prep: build Wcat hi/lo + bcat ----------------------
// c<512: Wskip|bskip.  512..1023: qWe col (h,m): w=Wq_h@We_row, b=bq·We_row.
// 1024..1535: qM col (h,u): w=Wq_h@Wk_row(u), b=bq·Wk_row(u).
// 1536..1539: dsc (h): w=Wq_h@(bk+be)_h, b=bq·(bk+be)_h.
__global__ __launch_bounds__(128) void prep_kernel(
    const float* __restrict__ Wq, const float* __restrict__ bq,
    const float* __restrict__ Wk, const float* __restrict__ bk,
    const float* __restrict__ We, const float* __restrict__ be,
    const float* __restrict__ Wskip, const float* __restrict__ bskip) {
    int c = blockIdx.x, t = threadIdx.x;
    __shared__ float wrow[128];
    float val, bias = 0.f;
    if (c < 512) {
        val = Wskip[t * HC + c];
        bias = bskip[c];
    } else if (c < 1536) {
        int cc = (c < 1024) ? (c - 512) : (c - 1024);
        int h = cc >> 7, m = cc & 127;
        wrow[t] = (c < 1024) ? We[m * HC + h * 128 + t] : Wk[m * HC + h * 128 + t];
        __syncthreads();
        float acc = 0.f;
        for (int d = 0; d < 128; d++) acc += Wq[t * HC + h * 128 + d] * wrow[d];
        val = acc;
        if (t == 0) {
            float bacc = 0.f;
            for (int d = 0; d < 128; d++) bacc += bq[h * 128 + d] * wrow[d];
            bias = bacc;
        }
    } else {
        int h = c - 1536;
        float acc = 0.f, bacc = 0.f;
        for (int d = 0; d < 128; d++) {
            float w = bk[h * 128 + d] + be[h * 128 + d];
            acc += Wq[t * HC + h * 128 + d] * w;
            bacc += bq[h * 128 + d] * w;
        }
        val = acc;
        if (t == 0) bias = bacc;
    }
    uint32_t hi = f2tf(val);
    g_Bhi0[t * STRD + c] = hi;
    g_Blo0[t * STRD + c] = f2tf(val - __uint_as_float(hi));
    if (t == 0) g_bcat[c] = bias;
}

__global__ void split_x_kernel(const float* __restrict__ x) {
    int t = blockIdx.x * 256 + threadIdx.x;
    if (t < NN * DD) {
        float v = x[t];
        uint32_t hi = f2tf(v);
        g_Ahi[t] = hi;
        g_Alo[t] = f2tf(v - __uint_as_float(hi));
    }
}

// ---------------- tensor-core SGEMM (3xTF32) ---------------------------------
__device__ __forceinline__ void mma8(float* c, const uint32_t* a, uint32_t b0, uint32_t b1) {
    asm volatile(
        "mma.sync.aligned.m16n8k8.row.col.f32.tf32.tf32.f32 "
        "{%0,%1,%2,%3}, {%4,%5,%6,%7}, {%8,%9}, {%0,%1,%2,%3};"
        : "+f"(c[0]), "+f"(c[1]), "+f"(c[2]), "+f"(c[3])
        : "r"(a[0]), "r"(a[1]), "r"(a[2]), "r"(a[3]), "r"(b0), "r"(b1));
}

// SEL 0: g_nodes = x @ Wcat + bcat (K=128, N=1540, pre-split, double-buffered)
// SEL 4: per head by: g_agge[:, by*128+c] = ut[:,by*256..] @ [Wv_h;We_h] + gate(bv+be)
// SEL 5: d_out = elu(g_normed @ Wlin + blin + x) (K=512, N=128)
template <int SEL>
__global__ __launch_bounds__(256, 2) void sgemm_tc(
    const float* __restrict__ Bin, const float* __restrict__ Bin2,
    const float* __restrict__ biasin, const float* __restrict__ bias2,
    const float* __restrict__ xres, float* __restrict__ Cout) {
    constexpr int K    = (SEL == 0) ? 128 : (SEL == 4) ? 256 : 512;
    constexpr int NTOT = (SEL == 0) ? STRD : DD;
    constexpr int CS   = (SEL == 0) ? STRD : (SEL == 4) ? HC : DD;
    constexpr int ASTR = (SEL == 4) ? 1024 : HC;
    const float* A = (SEL == 4) ? g_ut : g_normed;
    const float* bias_p = (SEL == 0) ? g_bcat : biasin;
    float* C = (SEL == 0) ? g_nodes : (SEL == 4) ? g_agge : Cout;

    extern __shared__ uint32_t smdyn[];

    int tid = threadIdx.x;
    int lane = tid & 31, w = tid >> 5;
    int g = lane >> 2, tig = lane & 3;
    int wm = w & 3, wn = w >> 2;
    int m0 = wm * 32, n0 = wn * 64;
    int row0 = blockIdx.x * 128;
    int col0 = (SEL == 4) ? 0 : blockIdx.y * 128;
    const int head = (SEL == 4) ? blockIdx.y : 0;
    const int acb = (SEL == 4) ? head * 256 : 0;
    const int cgb = (SEL == 4) ? head * 128 : col0;  // global C/bias column base

    float acc[2][8][4];
#pragma unroll
    for (int mt = 0; mt < 2; mt++)
#pragma unroll
        for (int nt = 0; nt < 8; nt++)
#pragma unroll
            for (int r = 0; r < 4; r++) acc[mt][nt][r] = 0.f;

    if (SEL == 0) {
        uint32_t shbase = (uint32_t)__cvta_generic_to_shared(smdyn);
        uint4 ahv[2], alv[2];
        auto ldA = [&](int kb) {
#pragma unroll
            for (int i = 0; i < 2; i++) {
                int qi = tid + i * 256;
                int m = qi >> 2, kq = qi & 3;
                int r = row0 + m;
                ahv[i] = make_uint4(0, 0, 0, 0);
                alv[i] = make_uint4(0, 0, 0, 0);
                if (r < NN) {
                    ahv[i] = *(const uint4*)&g_Ahi[(size_t)r * DD + kb + kq * 4];
                    alv[i] = *(const uint4*)&g_Alo[(size_t)r * DD + kb + kq * 4];
                }
            }
        };
        auto stA = [&](int b) {
#pragma unroll
            for (int i = 0; i < 2; i++) {
                int qi = tid + i * 256;
                int m = qi >> 2, kq = qi & 3;
                uint32_t hv[4] = {ahv[i].x, ahv[i].y, ahv[i].z, ahv[i].w};
                uint32_t lv[4] = {alv[i].x, alv[i].y, alv[i].z, alv[i].w};
#pragma unroll
                for (int j = 0; j < 4; j++) {
                    int kk = kq * 4 + j;
                    int idx = (b * 4) * TILEU + kk * BPAD + (m ^ ((kk >> 2) << 3));
                    smdyn[idx] = hv[j];
                    smdyn[idx + TILEU] = lv[j];
                }
            }
        };
        auto cpB = [&](int kb, int b) {
#pragma unroll
            for (int i = 0; i < 2; i++) {
                int qi = tid + i * 256;
                int kk = qi >> 5, nq = qi & 31;
                int c = col0 + nq * 4;
                int ehi = (b * 4 + 2) * TILEU + kk * BPAD + nq * 4;
                if (c + 4 <= NTOT) {
                    cp16(shbase + ehi * 4, &g_Bhi0[(size_t)(kb + kk) * STRD + c]);
                    cp16(shbase + (ehi + TILEU) * 4, &g_Blo0[(size_t)(kb + kk) * STRD + c]);
                } else {
                    *(uint4*)&smdyn[ehi] = make_uint4(0, 0, 0, 0);
                    *(uint4*)&smdyn[ehi + TILEU] = make_uint4(0, 0, 0, 0);
                }
            }
        };

        ldA(0);
        cpB(0, 0);
        asm volatile("cp.async.commit_group;");
        stA(0);
        asm volatile("cp.async.wait_group 0;");
        __syncthreads();

        const int T = K / 16;
        for (int it = 0; it < T; it++) {
            int cur = it & 1, nxt = cur ^ 1;
            bool more = (it + 1 < T);
            if (more) {
                ldA((it + 1) * 16);
                cpB((it + 1) * 16, nxt);
                asm volatile("cp.async.commit_group;");
            }
            uint32_t* sAhi = smdyn + (cur * 4) * TILEU;
            uint32_t* sAlo = sAhi + TILEU;
            uint32_t* sBhi = sAhi + 2 * TILEU;
            uint32_t* sBlo = sAhi + 3 * TILEU;
#pragma unroll
            for (int ks = 0; ks < 2; ks++) {
                int rlo = ks * 8 + tig, rhi = ks * 8 + tig + 4;
                int s1 = (rlo >> 2) << 3, s2 = (rhi >> 2) << 3;
                uint32_t ahi[2][4], alo[2][4];
#pragma unroll
                for (int mt = 0; mt < 2; mt++) {
                    int mb = m0 + mt * 16 + g;
                    ahi[mt][0] = sAhi[rlo * BPAD + (mb ^ s1)];
                    ahi[mt][1] = sAhi[rlo * BPAD + ((mb + 8) ^ s1)];
                    ahi[mt][2] = sAhi[rhi * BPAD + (mb ^ s2)];
                    ahi[mt][3] = sAhi[rhi * BPAD + ((mb + 8) ^ s2)];
                    alo[mt][0] = sAlo[rlo * BPAD + (mb ^ s1)];
                    alo[mt][1] = sAlo[rlo * BPAD + ((mb + 8) ^ s1)];
                    alo[mt][2] = sAlo[rhi * BPAD + (mb ^ s2)];
                    alo[mt][3] = sAlo[rhi * BPAD + ((mb + 8) ^ s2)];
                }
#pragma unroll
                for (int nt = 0; nt < 8; nt++) {
                    int nb = n0 + nt * 8 + g;
                    uint32_t bh0 = sBhi[rlo * BPAD + nb];
                    uint32_t bh1 = sBhi[rhi * BPAD + nb];
                    uint32_t bl0 = sBlo[rlo * BPAD + nb];
                    uint32_t bl1 = sBlo[rhi * BPAD + nb];
#pragma unroll
                    for (int mt = 0; mt < 2; mt++) {
                        mma8(acc[mt][nt], ahi[mt], bl0, bl1);
                        mma8(acc[mt][nt], alo[mt], bh0, bh1);
                        mma8(acc[mt][nt], ahi[mt], bh0, bh1);
                    }
                }
            }
            if (more) {
                stA(nxt);
                asm volatile("cp.async.wait_group 0;");
            }
            __syncthreads();
        }
    } else {
        // single-buffer convert-in-kernel path (SEL4 / SEL5)
        uint32_t* sAhi = smdyn;
        uint32_t* sAlo = smdyn + TILEU;
        uint32_t* sBhi = smdyn + 2 * TILEU;
        uint32_t* sBlo = smdyn + 3 * TILEU;
        for (int kb = 0; kb < K; kb += 16) {
            __syncthreads();
#pragma unroll
            for (int i = 0; i < 2; i++) {
                int qi = tid + i * 256;
                int m = qi >> 2, kq = qi & 3;
                int r = row0 + m;
                float4 av = make_float4(0.f, 0.f, 0.f, 0.f);
                if (r < NN) av = *(const float4*)&A[(size_t)r * ASTR + acb + kb + kq * 4];
                float vv[4] = {av.x, av.y, av.z, av.w};
#pragma unroll
                for (int j = 0; j < 4; j++) {
                    int kk = kq * 4 + j;
                    uint32_t hi = f2tf(vv[j]);
                    float lo = vv[j] - __uint_as_float(hi);
                    int idx = kk * BPAD + (m ^ ((kk >> 2) << 3));
                    sAhi[idx] = hi;
                    sAlo[idx] = f2tf(lo);
                }
            }
#pragma unroll
            for (int i = 0; i < 2; i++) {
                int qi = tid + i * 256;
                int kk = qi >> 5, nq = qi & 31;
                int c = cgb + nq * 4;
                float4 bv = make_float4(0.f, 0.f, 0.f, 0.f);
                int krow = kb + kk;
                if (nq * 4 + 4 <= NTOT) {
                    if (SEL == 4)
                        bv = (krow < 128)
                           ? *(const float4*)&Bin[(size_t)krow * HC + c]
                           : *(const float4*)&Bin2[(size_t)(krow - 128) * HC + c];
                    else
                        bv = *(const float4*)&Bin[(size_t)krow * NTOT + c];
                }
                float vv[4] = {bv.x, bv.y, bv.z, bv.w};
#pragma unroll
                for (int j = 0; j < 4; j++) {
                    uint32_t hi = f2tf(vv[j]);
                    float lo = vv[j] - __uint_as_float(hi);
                    sBhi[kk * BPAD + nq * 4 + j] = hi;
                    sBlo[kk * BPAD + nq * 4 + j] = f2tf(lo);
                }
            }
            __syncthreads();
#pragma unroll
            for (int ks = 0; ks < 2; ks++) {
                int rlo = ks * 8 + tig, rhi = ks * 8 + tig + 4;
                int s1 = (rlo >> 2) << 3, s2 = (rhi >> 2) << 3;
                uint32_t ahi[2][4], alo[2][4];
#pragma unroll
                for (int mt = 0; mt < 2; mt++) {
                    int mb = m0 + mt * 16 + g;
                    ahi[mt][0] = sAhi[rlo * BPAD + (mb ^ s1)];
                    ahi[mt][1] = sAhi[rlo * BPAD + ((mb + 8) ^ s1)];
                    ahi[mt][2] = sAhi[rhi * BPAD + (mb ^ s2)];
                    ahi[mt][3] = sAhi[rhi * BPAD + ((mb + 8) ^ s2)];
                    alo[mt][0] = sAlo[rlo * BPAD + (mb ^ s1)];
                    alo[mt][1] = sAlo[rlo * BPAD + ((mb + 8) ^ s1)];
                    alo[mt][2] = sAlo[rhi * BPAD + (mb ^ s2)];
                    alo[mt][3] = sAlo[rhi * BPAD + ((mb + 8) ^ s2)];
                }
#pragma unroll
                for (int nt = 0; nt < 8; nt++) {
                    int nb = n0 + nt * 8 + g;
                    uint32_t bh0 = sBhi[rlo * BPAD + nb];
                    uint32_t bh1 = sBhi[rhi * BPAD + nb];
                    uint32_t bl0 = sBlo[rlo * BPAD + nb];
                    uint32_t bl1 = sBlo[rhi * BPAD + nb];
#pragma unroll
                    for (int mt = 0; mt < 2; mt++) {
                        mma8(acc[mt][nt], ahi[mt], bl0, bl1);
                        mma8(acc[mt][nt], alo[mt], bh0, bh1);
                        mma8(acc[mt][nt], ahi[mt], bh0, bh1);
                    }
                }
            }
        }
    }

    // ---- epilogue ----
    float* stg = (float*)smdyn;
#pragma unroll
    for (int p = 0; p < 2; p++) {
        __syncthreads();
        if (wn == p) {
#pragma unroll
            for (int mt = 0; mt < 2; mt++)
#pragma unroll
                for (int nt = 0; nt < 8; nt++) {
                    int rl = m0 + mt * 16 + g;
                    int cl = nt * 8 + tig * 2;
                    stg[rl * 68 + cl]           = acc[mt][nt][0];
                    stg[rl * 68 + cl + 1]       = acc[mt][nt][1];
                    stg[(rl + 8) * 68 + cl]     = acc[mt][nt][2];
                    stg[(rl + 8) * 68 + cl + 1] = acc[mt][nt][3];
                }
        }
        __syncthreads();
#pragma unroll
        for (int i = 0; i < 8; i++) {
            int qi = tid + i * 256;
            int rl = qi >> 4, q4 = qi & 15;
            int grow = row0 + rl;
            int lcol = p * 64 + q4 * 4;
            int gcol = cgb + lcol;
            // SEL4: per-head local tile of 128 cols; others: global bound
            bool ok = (SEL == 4) ? (lcol + 4 <= NTOT) : (gcol + 4 <= NTOT);
            if (grow < NN && ok) {
                float4 v = *(float4*)&stg[rl * 68 + q4 * 4];
                float gate = 1.f;
                if (SEL == 4) gate = (g_count[grow] > 0) ? 1.f : 0.f;
                float o[4] = {v.x, v.y, v.z, v.w};
#pragma unroll
                for (int j = 0; j < 4; j++) {
                    if (SEL == 4) o[j] += gate * (biasin[gcol + j] + bias2[gcol + j]);
                    else          o[j] += bias_p[gcol + j];
                    if (SEL == 5) {
                        o[j] += xres[(size_t)grow * DD + gcol + j];
                        o[j] = (o[j] > 0.f) ? o[j] : expm1f(o[j]);
                    }
                }
                *(float4*)&C[(size_t)grow * CS + gcol] = make_float4(o[0], o[1], o[2], o[3]);
            }
        }
    }
}

// ---------------- CSR build --------------------------------------------------
__global__ void hist_kernel(const void* __restrict__ ei) {
    int t = blockIdx.x * 256 + threadIdx.x;
    if (t < EE) {
        int d = load_idx(ei, g_is64, (long long)EE + t);
        atomicAdd(&g_count[d], 1);
    }
}

__global__ __launch_bounds__(1024) void scan_kernel() {
    __shared__ int sh[1024];
    int t = threadIdx.x;
    int loc[16];
    int s = 0;
#pragma unroll
    for (int i = 0; i < 16; i++) {
        int idx = t * 16 + i;
        int cv = (idx < NN) ? g_count[idx] : 0;
        loc[i] = cv; s += cv;
    }
    sh[t] = s;
    __syncthreads();
    for (int off = 1; off < 1024; off <<= 1) {
        int v = (t >= off) ? sh[t - off] : 0;
        __syncthreads();
        sh[t] += v;
        __syncthreads();
    }
    int excl = sh[t] - s;
#pragma unroll
    for (int i = 0; i < 16; i++) {
        int idx = t * 16 + i;
        if (idx < NN) {
            g_off[idx] = excl;
            g_cur[idx] = excl;
            excl += loc[i];
        }
    }
}

__global__ void fill_kernel(const void* __restrict__ ei) {
    int t = blockIdx.x * 256 + threadIdx.x;
    if (t < EE) {
        int is64 = g_is64;
        int d = load_idx(ei, is64, (long long)EE + t);
        int pos = atomicAdd(&g_cur[d], 1);
        pos = min(max(pos, 0), EE - 1);
        g_elist[pos] = t;
        g_esrc[pos]  = load_idx(ei, is64, t);
    }
}

// ---------------- fused edge pass: x-space aggregation -----------------------
// alpha = qM[d]·x[s] (bias-inclusive) + qWe[d]·ea + dsc[d]; accumulate
// u_h = Σ ex·x[s], t_h = Σ ex·ea (128-dim each). Per-edge gathers: x[s] (512B)
// + ea (512B) only. 4 warps/node, barrier-free loop, single end merge.
__global__ __launch_bounds__(128) void agg_fused_kernel(
    const float* __restrict__ x, const float* __restrict__ ea) {
    int n = blockIdx.x;
    int l = threadIdx.x;
    int lane = l & 31, w = l >> 5;
    int off = g_off[n], cnt = g_count[n];
    int c4 = 4 * lane;

    float4 qm[4], qw[4];
    float dsc[4];
#pragma unroll
    for (int h = 0; h < 4; h++) {
        qm[h] = *(const float4*)&g_nodes[(size_t)n * STRD + QMOFF + h * 128 + c4];
        qw[h] = *(const float4*)&g_nodes[(size_t)n * STRD + QWEOFF + h * 128 + c4];
        dsc[h] = g_nodes[(size_t)n * STRD + DSCOFF + h];
    }

    float den[4] = {0.f, 0.f, 0.f, 0.f};
    float4 au[4], at[4];
#pragma unroll
    for (int h = 0; h < 4; h++) {
        au[h] = make_float4(0.f, 0.f, 0.f, 0.f);
        at[h] = make_float4(0.f, 0.f, 0.f, 0.f);
    }

    for (int k = w; k < cnt; k += 4) {
        int s   = g_esrc[off + k];
        int eid = g_elist[off + k];
        float4 x4  = __ldg((const float4*)&x[(size_t)s * DD + c4]);
        float4 ea4 = __ldg((const float4*)&ea[(size_t)eid * DD + c4]);
        float p[4];
#pragma unroll
        for (int h = 0; h < 4; h++) {
            p[h] = qm[h].x * x4.x + qm[h].y * x4.y
                 + qm[h].z * x4.z + qm[h].w * x4.w
                 + qw[h].x * ea4.x + qw[h].y * ea4.y
                 + qw[h].z * ea4.z + qw[h].w * ea4.w;
        }
#pragma unroll
        for (int offs = 16; offs > 0; offs >>= 1) {
#pragma unroll
            for (int h = 0; h < 4; h++)
                p[h] += __shfl_xor_sync(0xffffffffu, p[h], offs);
        }
        float ex[4];
#pragma unroll
        for (int h = 0; h < 4; h++) {
            ex[h] = expf((p[h] + dsc[h]) * RSQRT_D);
            den[h] += ex[h];
            au[h].x += ex[h] * x4.x;  au[h].y += ex[h] * x4.y;
            au[h].z += ex[h] * x4.z;  au[h].w += ex[h] * x4.w;
            at[h].x += ex[h] * ea4.x; at[h].y += ex[h] * ea4.y;
            at[h].z += ex[h] * ea4.z; at[h].w += ex[h] * ea4.w;
        }
    }

    // merge 4 warps via smem
    __shared__ float su[4][HC], st_[4][HC];
    __shared__ float sd[4][HH];
#pragma unroll
    for (int h = 0; h < 4; h++) {
        *(float4*)&su[w][h * 128 + c4]  = au[h];
        *(float4*)&st_[w][h * 128 + c4] = at[h];
    }
    if (lane < 4) sd[w][lane] = den[lane];
    __syncthreads();

    int ho = l >> 5;
    int m = 4 * (l & 31);
    float d = sd[0][ho] + sd[1][ho] + sd[2][ho] + sd[3][ho];
    float rd = (cnt > 0) ? 1.f / d : 0.f;
    float4 ru = make_float4(0.f, 0.f, 0.f, 0.f), rt = make_float4(0.f, 0.f, 0.f, 0.f);
#pragma unroll
    for (int ww = 0; ww < 4; ww++) {
        float4 a = *(float4*)&su[ww][ho * 128 + m];
        float4 b = *(float4*)&st_[ww][ho * 128 + m];
        ru.x += a.x; ru.y += a.y; ru.z += a.z; ru.w += a.w;
        rt.x += b.x; rt.y += b.y; rt.z += b.z; rt.w += b.w;
    }
    *(float4*)&g_ut[(size_t)n * 1024 + ho * 256 + m] =
        make_float4(ru.x * rd, ru.y * rd, ru.z * rd, ru.w * rd);
    *(float4*)&g_ut[(size_t)n * 1024 + ho * 256 + 128 + m] =
        make_float4(rt.x * rd, rt.y * rd, rt.z * rd, rt.w * rd);
}

// ---------------- LayerNorm over HC=512 (agge + skip) ------------------------
__global__ __launch_bounds__(128) void ln_kernel(
    const float* __restrict__ g, const float* __restrict__ b) {
    int n = blockIdx.x;
    int tid = threadIdx.x;
    float vals[4];
    float s = 0.f, s2 = 0.f;
#pragma unroll
    for (int j = 0; j < 4; j++) {
        int c = tid + j * 128;
        float o = g_agge[(size_t)n * HC + c] + g_nodes[(size_t)n * STRD + SKOFF + c];
        vals[j] = o; s += o; s2 += o * o;
    }
    __shared__ float sh[8];
#pragma unroll
    for (int off = 16; off > 0; off >>= 1) {
        s  += __shfl_xor_sync(0xffffffffu, s, off);
        s2 += __shfl_xor_sync(0xffffffffu, s2, off);
    }
    int wid = tid >> 5, lane = tid & 31;
    if (lane == 0) { sh[wid] = s; sh[4 + wid] = s2; }
    __syncthreads();
    s  = sh[0] + sh[1] + sh[2] + sh[3];
    s2 = sh[4] + sh[5] + sh[6] + sh[7];
    float mu = s * (1.f / 512.f);
    float var = s2 * (1.f / 512.f) - mu * mu;
    float rs = rsqrtf(var + 1e-5f);
#pragma unroll
    for (int j = 0; j < 4; j++) {
        int c = tid + j * 128;
        g_normed[(size_t)n * HC + c] = (vals[j] - mu) * rs * g[c] + b[c];
    }
}

// ---------------- launch -----------------------------------------------------
extern "C" void kernel_launch(void* const* d_in, const int* in_sizes, int n_in,
                              void* d_out, int out_size) {
    const float* x     = (const float*)d_in[0];
    const void*  ei    = d_in[1];
    const float* ea    = (const float*)d_in[2];
    const float* Wq    = (const float*)d_in[3];
    const float* bq    = (const float*)d_in[4];
    const float* Wk    = (const float*)d_in[5];
    const float* bk    = (const float*)d_in[6];
    const float* Wv    = (const float*)d_in[7];
    const float* bv    = (const float*)d_in[8];
    const float* We    = (const float*)d_in[9];
    const float* be    = (const float*)d_in[10];
    const float* Wskip = (const float*)d_in[11];
    const float* bskip = (const float*)d_in[12];
    const float* ln_g  = (const float*)d_in[13];
    const float* ln_b  = (const float*)d_in[14];
    const float* Wlin  = (const float*)d_in[15];
    const float* blin  = (const float*)d_in[16];

    const int SMEM_DB = 2 * 4 * TILEU * 4;
    const int SMEM_SB = 4 * TILEU * 4;
    cudaFuncSetAttribute(sgemm_tc<0>, cudaFuncAttributeMaxDynamicSharedMemorySize, SMEM_DB);

    detect_kernel<<<1, 32>>>(ei);
    zero_kernel<<<(NN + 255) / 256, 256>>>();
    prep_kernel<<<STRD, 128>>>(Wq, bq, Wk, bk, We, be, Wskip, bskip);
    split_x_kernel<<<(NN * DD + 255) / 256, 256>>>(x);

    dim3 g0((NN + 127) / 128, (STRD + 127) / 128);
    sgemm_tc<0><<<g0, 256, SMEM_DB>>>(nullptr, nullptr, nullptr, nullptr, nullptr, nullptr);

    hist_kernel<<<(EE + 255) / 256, 256>>>(ei);
    scan_kernel<<<1, 1024>>>();
    fill_kernel<<<(EE + 255) / 256, 256>>>(ei);

    agg_fused_kernel<<<NN, 128>>>(x, ea);

    dim3 g4((NN + 127) / 128, HH);
    sgemm_tc<4><<<g4, 256, SMEM_SB>>>(Wv, We, bv, be, nullptr, nullptr);

    ln_kernel<<<NN, 128>>>(ln_g, ln_b);

    dim3 g5((NN + 127) / 128, 1);
    sgemm_tc<5><<<g5, 256, SMEM_SB>>>(Wlin, nullptr, blin, nullptr, x, (float*)d_out);
}